// round 1
// baseline (speedup 1.0000x reference)
#include <cuda_runtime.h>
#include <math.h>

// ---------------------------------------------------------------------------
// Problem constants (match reference)
// ---------------------------------------------------------------------------
#define BATCH 16
#define NH    128
#define L0    16384
#define KS    4
#define STRIDE 2
#define DEPTHS 13
#define LMAX  8192          // row pitch for intermediate buffers (>= max Lout)
#define T_OUT 32            // output positions per block
#define TIN   (2*T_OUT + 2) // 66 input positions per tile
#define CIN   129           // 128 h channels + 1 depth channel

// ---------------------------------------------------------------------------
// Device scratch (static, allocation-free)
// ---------------------------------------------------------------------------
__device__ float g_bufA[(size_t)BATCH * NH * LMAX];
__device__ float g_bufB[(size_t)BATCH * NH * LMAX];
__device__ float g_Wt[516 * 384];          // transposed weights: [c*4+k][j]
__device__ float g_capture[BATCH * NH];    // h[:, :, 0] at finish depth
__device__ int   g_Nseq[BATCH][DEPTHS + 1];
__device__ int   g_finish[BATCH];
__device__ int   g_rank[BATCH];

// ---------------------------------------------------------------------------
// Prep: N recurrence, finish depth, stable rank (argsort by finish)
// ---------------------------------------------------------------------------
__global__ void prep_meta_kernel(const int* __restrict__ N)
{
    __shared__ int fin[BATCH];
    int b = threadIdx.x;
    if (b < BATCH) {
        int n = N[b];
        g_Nseq[b][0] = n;
        int f = DEPTHS - 1;
        bool done = false;
        #pragma unroll
        for (int d = 0; d < DEPTHS; ++d) {
            int m = n - KS; if (m < 0) m = 0;
            n = (m + 1) / 2 + 1;
            g_Nseq[b][d + 1] = n;
            if (!done && n <= 1) { f = d; done = true; }
        }
        fin[b] = f;
        g_finish[b] = f;
    }
    __syncthreads();
    if (b < BATCH) {
        int f = fin[b];
        int r = 0;
        #pragma unroll
        for (int j = 0; j < BATCH; ++j)
            if (fin[j] < f || (fin[j] == f && j < b)) r++;
        g_rank[b] = r;
    }
}

// ---------------------------------------------------------------------------
// Prep: transpose W [384][129][4] -> g_Wt [516][384] for coalesced loads
// ---------------------------------------------------------------------------
__global__ void prep_wt_kernel(const float* __restrict__ W)
{
    int i = blockIdx.x * blockDim.x + threadIdx.x;
    if (i < 384 * 516) {
        int j  = i / 516;   // output channel (0..383)
        int ck = i % 516;   // c*4 + k
        g_Wt[ck * 384 + j] = W[i];
    }
}

// ---------------------------------------------------------------------------
// One depth step: conv(KS=4, stride=2) + bias + gated update.
//   in  : [B][128][in_stride] (masked virtually by pos < V)
//   out : [B][128][8192]
// Block: (tile of 32 output positions) x (batch). 256 threads:
//   o = tid & 127 (output channel), half = tid >> 7 selects 16 of the 32 t's.
// ---------------------------------------------------------------------------
__global__ __launch_bounds__(256)
void conv_step_kernel(const float* __restrict__ hin,
                      int insel,          // 0: hin, 1: g_bufA, 2: g_bufB
                      int outsel,         // 1: g_bufA, 2: g_bufB
                      int in_stride, int Lc, int Lout,
                      int depth, float logd,
                      const float* __restrict__ bias)
{
    const int b  = blockIdx.y;
    const int t0 = blockIdx.x * T_OUT;

    // Skip whole tiles whose outputs are dead (>= N_{d+1}); t0==0 always runs.
    const int Nn = g_Nseq[b][depth + 1];
    if (t0 >= Nn) return;

    const float* in = (insel == 0) ? hin : (insel == 1 ? g_bufA : g_bufB);
    float* out = (outsel == 1) ? g_bufA : g_bufB;

    __shared__ float tile[CIN][TIN];

    const int V = min(Lc, g_Nseq[b][depth]);   // valid input positions
    const float* inb = in + (size_t)b * NH * in_stride;

    // Cooperative tile load (coalesced along pos)
    for (int i = threadIdx.x; i < CIN * TIN; i += 256) {
        int c = i / TIN;
        int x = i - c * TIN;
        int pos = 2 * t0 + x;
        float v = 0.0f;
        if (pos < V) v = (c < NH) ? inb[(size_t)c * in_stride + pos] : logd;
        tile[c][x] = v;
    }
    __syncthreads();

    const int o    = threadIdx.x & 127;
    const int half = threadIdx.x >> 7;
    const int tl0  = half * 16;

    float accl[16], accr[16], accg[16];
    const float bl = bias[o], br = bias[NH + o], bg = bias[2 * NH + o];
    #pragma unroll
    for (int tt = 0; tt < 16; ++tt) { accl[tt] = bl; accr[tt] = br; accg[tt] = bg; }

    #pragma unroll 2
    for (int c = 0; c < CIN; ++c) {
        const float* wp = g_Wt + c * 4 * 384;
        float wl[4], wr[4], wg[4];
        #pragma unroll
        for (int k = 0; k < 4; ++k) {
            wl[k] = wp[k * 384 + o];
            wr[k] = wp[k * 384 + NH + o];
            wg[k] = wp[k * 384 + 2 * NH + o];
        }
        const float* hrow = &tile[c][2 * tl0];
        float h0 = hrow[0];
        float h1 = hrow[1];
        #pragma unroll
        for (int tt = 0; tt < 16; ++tt) {
            float h2 = hrow[2 * tt + 2];
            float h3 = hrow[2 * tt + 3];
            accl[tt] += wl[0] * h0 + wl[1] * h1 + wl[2] * h2 + wl[3] * h3;
            accr[tt] += wr[0] * h0 + wr[1] * h1 + wr[2] * h2 + wr[3] * h3;
            accg[tt] += wg[0] * h0 + wg[1] * h1 + wg[2] * h2 + wg[3] * h3;
            h0 = h2; h1 = h3;
        }
    }

    const int fin_here = (g_finish[b] == depth);
    float* outb = out + ((size_t)b * NH + o) * LMAX;
    #pragma unroll
    for (int tt = 0; tt < 16; ++tt) {
        int t = t0 + tl0 + tt;
        if (t < Lout) {
            float g  = 1.0f / (1.0f + expf(-accg[tt]));
            float r  = tanhf(accr[tt]);
            float hn = accl[tt] * g + r * (1.0f - g);
            outb[t] = hn;
            if (t == 0 && fin_here) g_capture[b * NH + o] = hn;
        }
    }
}

// ---------------------------------------------------------------------------
// Final: out[rank[b]] = capture[b]
// ---------------------------------------------------------------------------
__global__ void finalize_kernel(float* __restrict__ out)
{
    int b = blockIdx.x;
    int o = threadIdx.x;
    out[g_rank[b] * NH + o] = g_capture[b * NH + o];
}

// ---------------------------------------------------------------------------
// Launch
// ---------------------------------------------------------------------------
extern "C" void kernel_launch(void* const* d_in, const int* in_sizes, int n_in,
                              void* d_out, int out_size)
{
    const float* h    = (const float*)d_in[0];
    const int*   N    = (const int*)  d_in[1];
    const float* W    = (const float*)d_in[2];
    const float* bias = (const float*)d_in[3];
    float* out = (float*)d_out;

    prep_meta_kernel<<<1, 32>>>(N);
    prep_wt_kernel<<<(384 * 516 + 255) / 256, 256>>>(W);

    // Depth schedule (deterministic from L0)
    static const int Lin[DEPTHS]  = {16384, 8191, 4095, 2047, 1023, 511, 255,
                                     127, 63, 31, 15, 7, 3};
    static const int LoutA[DEPTHS] = {8191, 4095, 2047, 1023, 511, 255, 127,
                                      63, 31, 15, 7, 3, 1};

    for (int d = 0; d < DEPTHS; ++d) {
        int insel  = (d == 0) ? 0 : ((d & 1) ? 1 : 2);  // d1 reads A, d2 reads B,...
        int outsel = (d & 1) ? 2 : 1;                   // d0 writes A, d1 writes B,...
        int in_stride = (d == 0) ? L0 : LMAX;
        float logd = log1pf((float)d);
        dim3 grid((LoutA[d] + T_OUT - 1) / T_OUT, BATCH);
        conv_step_kernel<<<grid, 256>>>(h, insel, outsel, in_stride,
                                        Lin[d], LoutA[d], d, logd, bias);
    }

    finalize_kernel<<<BATCH, NH>>>(out);
}

// round 2
// speedup vs baseline: 1.3311x; 1.3311x over previous
#include <cuda_runtime.h>
#include <math.h>

// ---------------------------------------------------------------------------
// Problem constants
// ---------------------------------------------------------------------------
#define BATCH 16
#define NH    128
#define L0    16384
#define KS    4
#define STRIDE 2
#define DEPTHS 13
#define LMAX  8192
#define T_OUT 16            // output positions per block
#define TPT   8             // t's per thread (two halves of 128 threads)
#define TIN   (2*T_OUT + 2) // 34 input positions per tile
#define CIN   129           // 128 h channels + 1 depth channel

// ---------------------------------------------------------------------------
// Device scratch (static, allocation-free)
// ---------------------------------------------------------------------------
__device__ float  g_bufA[(size_t)BATCH * NH * LMAX];
__device__ float  g_bufB[(size_t)BATCH * NH * LMAX];
__device__ float4 g_W4[CIN * 3 * NH];      // [c][gate][o] -> (k0,k1,k2,k3)
__device__ float  g_capture[BATCH * NH];
__device__ int    g_Nseq[BATCH][DEPTHS + 1];
__device__ int    g_finish[BATCH];
__device__ int    g_rank[BATCH];

// ---------------------------------------------------------------------------
// Packed f32x2 FMA (Blackwell): lane-wise d = a*b + c on 2x fp32
// ---------------------------------------------------------------------------
__device__ __forceinline__ unsigned long long fma2(unsigned long long a,
                                                   unsigned long long b,
                                                   unsigned long long c)
{
    unsigned long long d;
    asm("fma.rn.f32x2 %0, %1, %2, %3;" : "=l"(d) : "l"(a), "l"(b), "l"(c));
    return d;
}

__device__ __forceinline__ float lane_lo(unsigned long long v)
{ return __uint_as_float((unsigned)(v & 0xffffffffull)); }
__device__ __forceinline__ float lane_hi(unsigned long long v)
{ return __uint_as_float((unsigned)(v >> 32)); }

// ---------------------------------------------------------------------------
// Prep: N recurrence, finish depth, stable rank
// ---------------------------------------------------------------------------
__global__ void prep_meta_kernel(const int* __restrict__ N)
{
    __shared__ int fin[BATCH];
    int b = threadIdx.x;
    if (b < BATCH) {
        int n = N[b];
        g_Nseq[b][0] = n;
        int f = DEPTHS - 1;
        bool done = false;
        #pragma unroll
        for (int d = 0; d < DEPTHS; ++d) {
            int m = n - KS; if (m < 0) m = 0;
            n = (m + 1) / 2 + 1;
            g_Nseq[b][d + 1] = n;
            if (!done && n <= 1) { f = d; done = true; }
        }
        fin[b] = f;
        g_finish[b] = f;
    }
    __syncthreads();
    if (b < BATCH) {
        int f = fin[b];
        int r = 0;
        #pragma unroll
        for (int j = 0; j < BATCH; ++j)
            if (fin[j] < f || (fin[j] == f && j < b)) r++;
        g_rank[b] = r;
    }
}

// ---------------------------------------------------------------------------
// Prep: repack W [384][129][4] -> g_W4[(c*3+gate)*128+o] = float4(k0..k3)
// ---------------------------------------------------------------------------
__global__ void prep_wt_kernel(const float* __restrict__ W)
{
    int i = blockIdx.x * blockDim.x + threadIdx.x;  // over 129*3*128 float4s
    if (i < CIN * 3 * NH) {
        int o    = i & 127;
        int gate = (i >> 7) % 3;
        int c    = i / (3 * NH);
        int j    = gate * NH + o;
        const float4* src = reinterpret_cast<const float4*>(W);
        g_W4[i] = src[j * CIN + c];   // W[j][c][0..3], 16B aligned
    }
}

// ---------------------------------------------------------------------------
// One depth step: conv(KS=4, stride=2) + bias + gated update, f32x2-packed.
// Block: 256 threads = 128 output channels x 2 halves of 8 t's each.
// ---------------------------------------------------------------------------
__global__ __launch_bounds__(256)
void conv_step_kernel(const float* __restrict__ hin,
                      int insel, int outsel,
                      int in_stride, int Lc, int Lout,
                      int depth, float logd,
                      const float* __restrict__ bias)
{
    const int b  = blockIdx.y;
    const int t0 = blockIdx.x * T_OUT;

    const int Nn = g_Nseq[b][depth + 1];
    if (t0 >= Nn) return;   // whole tile dead (outputs would be masked next step)

    const float* in = (insel == 0) ? hin : (insel == 1 ? g_bufA : g_bufB);
    float* out = (outsel == 1) ? g_bufA : g_bufB;

    __shared__ float tile[CIN][TIN];   // TIN=34 floats (136B rows, 8B aligned)

    const int V = min(Lc, g_Nseq[b][depth]);
    const float* inb = in + (size_t)b * NH * in_stride;

    for (int i = threadIdx.x; i < CIN * TIN; i += 256) {
        int c = i / TIN;
        int x = i - c * TIN;
        int pos = 2 * t0 + x;
        float v = 0.0f;
        if (pos < V) v = (c < NH) ? inb[(size_t)c * in_stride + pos] : logd;
        tile[c][x] = v;
    }
    __syncthreads();

    const int o    = threadIdx.x & 127;
    const int half = threadIdx.x >> 7;
    const int tl0  = half * TPT;

    unsigned long long accl[TPT], accr[TPT], accg[TPT];
    #pragma unroll
    for (int tt = 0; tt < TPT; ++tt) { accl[tt] = 0ull; accr[tt] = 0ull; accg[tt] = 0ull; }

    const ulonglong2* wbase = reinterpret_cast<const ulonglong2*>(g_W4);

    #pragma unroll 1
    for (int c = 0; c < CIN; ++c) {
        const ulonglong2 wl = wbase[(c * 3 + 0) * NH + o];  // (k0,k1)|(k2,k3)
        const ulonglong2 wr = wbase[(c * 3 + 1) * NH + o];
        const ulonglong2 wg = wbase[(c * 3 + 2) * NH + o];
        // x2[j] = (tile[c][2j], tile[c][2j+1]); 8B-aligned, warp-broadcast LDS.64
        const unsigned long long* xr =
            reinterpret_cast<const unsigned long long*>(&tile[c][2 * tl0]);
        unsigned long long x0 = xr[0];
        #pragma unroll
        for (int tt = 0; tt < TPT; ++tt) {
            unsigned long long x1 = xr[tt + 1];
            accl[tt] = fma2(wl.x, x0, accl[tt]);
            accl[tt] = fma2(wl.y, x1, accl[tt]);
            accr[tt] = fma2(wr.x, x0, accr[tt]);
            accr[tt] = fma2(wr.y, x1, accr[tt]);
            accg[tt] = fma2(wg.x, x0, accg[tt]);
            accg[tt] = fma2(wg.y, x1, accg[tt]);
            x0 = x1;
        }
    }

    const float bl = bias[o], br = bias[NH + o], bg = bias[2 * NH + o];
    const int fin_here = (g_finish[b] == depth);
    float* outb = out + ((size_t)b * NH + o) * LMAX;

    #pragma unroll
    for (int tt = 0; tt < TPT; ++tt) {
        int t = t0 + tl0 + tt;
        if (t < Lout) {
            float l  = lane_lo(accl[tt]) + lane_hi(accl[tt]) + bl;
            float rr = lane_lo(accr[tt]) + lane_hi(accr[tt]) + br;
            float gg = lane_lo(accg[tt]) + lane_hi(accg[tt]) + bg;
            float g  = 1.0f / (1.0f + __expf(-gg));
            float r  = tanhf(rr);
            float hn = l * g + r * (1.0f - g);
            outb[t] = hn;
            if (t == 0 && fin_here) g_capture[b * NH + o] = hn;
        }
    }
}

// ---------------------------------------------------------------------------
// Final: out[rank[b]] = capture[b]
// ---------------------------------------------------------------------------
__global__ void finalize_kernel(float* __restrict__ out)
{
    int b = blockIdx.x;
    int o = threadIdx.x;
    out[g_rank[b] * NH + o] = g_capture[b * NH + o];
}

// ---------------------------------------------------------------------------
// Launch
// ---------------------------------------------------------------------------
extern "C" void kernel_launch(void* const* d_in, const int* in_sizes, int n_in,
                              void* d_out, int out_size)
{
    const float* h    = (const float*)d_in[0];
    const int*   N    = (const int*)  d_in[1];
    const float* W    = (const float*)d_in[2];
    const float* bias = (const float*)d_in[3];
    float* out = (float*)d_out;

    prep_meta_kernel<<<1, 32>>>(N);
    prep_wt_kernel<<<(CIN * 3 * NH + 255) / 256, 256>>>(W);

    static const int Lin[DEPTHS]   = {16384, 8191, 4095, 2047, 1023, 511, 255,
                                      127, 63, 31, 15, 7, 3};
    static const int LoutA[DEPTHS] = {8191, 4095, 2047, 1023, 511, 255, 127,
                                      63, 31, 15, 7, 3, 1};

    for (int d = 0; d < DEPTHS; ++d) {
        int insel  = (d == 0) ? 0 : ((d & 1) ? 1 : 2);
        int outsel = (d & 1) ? 2 : 1;
        int in_stride = (d == 0) ? L0 : LMAX;
        float logd = log1pf((float)d);
        dim3 grid((LoutA[d] + T_OUT - 1) / T_OUT, BATCH);
        conv_step_kernel<<<grid, 256>>>(h, insel, outsel, in_stride,
                                        Lin[d], LoutA[d], d, logd, bias);
    }

    finalize_kernel<<<BATCH, NH>>>(out);
}